// round 2
// baseline (speedup 1.0000x reference)
#include <cuda_runtime.h>

#define NN 10000
#define NE 80000

__device__ __constant__ int c_EXPAND[9] = {0,1,1,1,2,2,2,2,2};

// ---------------- scratch (static device arrays; no allocation) ----------------
__device__ float g_xn  [NN*576];    // enorm(x)
__device__ float g_rad [NE*384];    // radial features (E,3,128)
__device__ float g_val0[NE*128];    // silu(g_scalar)
__device__ float g_gdir[NE*256];    // sigmoid dir gates (E,2,128)
__device__ float g_gten[NE*256];    // sigmoid ten gates (E,2,128)
__device__ float g_e   [NE*8];      // exp(logits)
__device__ float g_num [NN*1152];   // attn-weighted message numerator
__device__ float g_den [NN*8];      // attn denominator
__device__ float g_x1  [NN*576];    // x after first residual
__device__ float g_yn  [NN*576];    // enorm(x1)
__device__ float g_gsil[NN*128];    // silu(gate)
__device__ float g_gsig[NN*128];    // sigmoid(gate)

__device__ __forceinline__ float sigm(float z) { return 1.f / (1.f + __expf(-z)); }

// ---------------- zero accumulators ----------------
__global__ void zero_kernel() {
    int i = blockIdx.x * blockDim.x + threadIdx.x;
    if (i < NN*1152) g_num[i] = 0.f;
    if (i < NN*8)    g_den[i] = 0.f;
}

// ---------------- equivariant norm: dst = enorm(src) ----------------
__global__ void enorm_kernel(const float* __restrict__ src, float* __restrict__ dst) {
    int n = blockIdx.x, c = threadIdx.x;   // 64 threads
    const float* p = src + n*576 + c;
    float v[9];
#pragma unroll
    for (int k = 0; k < 9; k++) v[k] = p[k*64];
    float s0 = v[0]*v[0];
    float s1 = v[1]*v[1] + v[2]*v[2] + v[3]*v[3];
    float s2 = v[4]*v[4] + v[5]*v[5] + v[6]*v[6] + v[7]*v[7] + v[8]*v[8];
#pragma unroll
    for (int off = 16; off; off >>= 1) {
        s0 += __shfl_xor_sync(0xffffffffu, s0, off);
        s1 += __shfl_xor_sync(0xffffffffu, s1, off);
        s2 += __shfl_xor_sync(0xffffffffu, s2, off);
    }
    __shared__ float red[3][2];
    if ((c & 31) == 0) { red[0][c>>5] = s0; red[1][c>>5] = s1; red[2][c>>5] = s2; }
    __syncthreads();
    float t0 = red[0][0] + red[0][1];
    float t1 = red[1][0] + red[1][1];
    float t2 = red[2][0] + red[2][1];
    float sc0 = rsqrtf(t0 * (1.f/64.f)  + 1e-6f);
    float sc1 = rsqrtf(t1 * (1.f/192.f) + 1e-6f);
    float sc2 = rsqrtf(t2 * (1.f/320.f) + 1e-6f);
    float* q = dst + n*576 + c;
    q[0] = v[0]*sc0;
#pragma unroll
    for (int k = 1; k < 4; k++) q[k*64] = v[k]*sc1;
#pragma unroll
    for (int k = 4; k < 9; k++) q[k*64] = v[k]*sc2;
}

// ---------------- radial MLP: rad = silu(ef@W1+b1)@W2+b2 ----------------
__global__ void __launch_bounds__(128) rad_kernel(
    const float* __restrict__ edist, const float* __restrict__ semb,
    const float* __restrict__ temb,  const float* __restrict__ W1,
    const float* __restrict__ b1,    const float* __restrict__ W2,
    const float* __restrict__ b2,    const int* __restrict__ anum,
    const int* __restrict__ eidx)
{
    __shared__ float ef[128][20];   // [c][e], 16 edges + pad
    __shared__ float h1[128][20];
    __shared__ int zsrc[16], ztgt[16];
    int e0 = blockIdx.x * 16, t = threadIdx.x;
    if (t < 16)       zsrc[t]    = anum[eidx[e0 + t]];
    else if (t < 32)  ztgt[t-16] = anum[eidx[NE + e0 + t - 16]];
    __syncthreads();
#pragma unroll
    for (int e = 0; e < 16; e++) {
        float v;
        if (t < 64)      v = edist[(e0+e)*64 + t];
        else if (t < 96) v = semb[zsrc[e]*32 + (t-64)];
        else             v = temb[ztgt[e]*32 + (t-96)];
        ef[t][e] = v;
    }
    __syncthreads();
    {
        float acc[16];
#pragma unroll
        for (int e = 0; e < 16; e++) acc[e] = 0.f;
        const float* W = W1 + t;
#pragma unroll 4
        for (int c = 0; c < 128; c++) {
            float w = W[c*128];
            const float4* xr = (const float4*)&ef[c][0];
#pragma unroll
            for (int e4 = 0; e4 < 4; e4++) {
                float4 xv = xr[e4];
                acc[e4*4+0] += w*xv.x; acc[e4*4+1] += w*xv.y;
                acc[e4*4+2] += w*xv.z; acc[e4*4+3] += w*xv.w;
            }
        }
        float bb = b1[t];
#pragma unroll
        for (int e = 0; e < 16; e++) { float z = acc[e] + bb; h1[t][e] = z * sigm(z); }
    }
    __syncthreads();
    for (int j = 0; j < 3; j++) {
        int o = j*128 + t;
        float acc[16];
#pragma unroll
        for (int e = 0; e < 16; e++) acc[e] = 0.f;
        const float* W = W2 + o;
#pragma unroll 4
        for (int c = 0; c < 128; c++) {
            float w = W[c*384];
            const float4* xr = (const float4*)&h1[c][0];
#pragma unroll
            for (int e4 = 0; e4 < 4; e4++) {
                float4 xv = xr[e4];
                acc[e4*4+0] += w*xv.x; acc[e4*4+1] += w*xv.y;
                acc[e4*4+2] += w*xv.z; acc[e4*4+3] += w*xv.w;
            }
        }
        float bb = b2[o];
#pragma unroll
        for (int e = 0; e < 16; e++) g_rad[(e0+e)*384 + o] = acc[e] + bb;
    }
}

// ---------------- extra = x_edge[:,0]@W_m0 ; gates / val0 / attention logits ----------------
__global__ void __launch_bounds__(128) extra_kernel(
    const float* __restrict__ Wm0, const float* __restrict__ lng,
    const float* __restrict__ lnb, const float* __restrict__ adot,
    const int* __restrict__ eidx)
{
    __shared__ float xe0[128][20];
    __shared__ float chunk[16][128];
    __shared__ int src_s[16], tgt_s[16];
    int e0 = blockIdx.x * 16, t = threadIdx.x;
    if (t < 16)      src_s[t]    = eidx[e0 + t];
    else if (t < 32) tgt_s[t-16] = eidx[NE + e0 + t - 16];
    __syncthreads();
#pragma unroll
    for (int e = 0; e < 16; e++) {
        float xv = (t < 64) ? g_xn[src_s[e]*576 + t] : g_xn[tgt_s[e]*576 + (t-64)];
        xe0[t][e] = xv * g_rad[(e0+e)*384 + t];   // deg-0 radial block
    }
    __syncthreads();
    for (int oc = 0; oc < 7; oc++) {
        float acc[16];
#pragma unroll
        for (int e = 0; e < 16; e++) acc[e] = 0.f;
        const float* W = Wm0 + oc*128 + t;
#pragma unroll 4
        for (int c = 0; c < 128; c++) {
            float w = W[c*896];
            const float4* xr = (const float4*)&xe0[c][0];
#pragma unroll
            for (int e4 = 0; e4 < 4; e4++) {
                float4 xv = xr[e4];
                acc[e4*4+0] += w*xv.x; acc[e4*4+1] += w*xv.y;
                acc[e4*4+2] += w*xv.z; acc[e4*4+3] += w*xv.w;
            }
        }
        if (oc < 2) {                       // alpha_f chunk: heads 4*oc .. 4*oc+3
#pragma unroll
            for (int e = 0; e < 16; e++) chunk[e][t] = acc[e];
            __syncthreads();
            if (t < 64) {
                int e = t >> 2, h4 = t & 3, h = oc*4 + h4;
                const float* ap = &chunk[e][h4*32];
                float m = 0.f, m2 = 0.f;
#pragma unroll
                for (int a = 0; a < 32; a++) { float v = ap[a]; m += v; m2 += v*v; }
                m *= (1.f/32.f);
                float var = m2*(1.f/32.f) - m*m;
                float rs = rsqrtf(var + 1e-5f);
                float logit = 0.f;
#pragma unroll
                for (int a = 0; a < 32; a++) {
                    float an = (ap[a] - m)*rs*lng[a] + lnb[a];
                    float sl = 0.2f*an + 0.8f*an*sigm(an);
                    logit += sl * adot[h*32 + a];
                }
                float ee = __expf(logit);
                g_e[(e0+e)*8 + h] = ee;
                atomicAdd(&g_den[tgt_s[e]*8 + h], ee);
            }
            __syncthreads();
        } else if (oc == 2) {               // g_scalar -> silu
#pragma unroll
            for (int e = 0; e < 16; e++) { float z = acc[e]; g_val0[(e0+e)*128 + t] = z * sigm(z); }
        } else {                            // gates: oc=3,4 -> dir(l=0,1); oc=5,6 -> ten(l=0,1)
            int which = oc - 3;
#pragma unroll
            for (int e = 0; e < 16; e++) {
                float s = sigm(acc[e]);
                if (which < 2) g_gdir[(e0+e)*256 + which*128 + t] = s;
                else           g_gten[(e0+e)*256 + (which-2)*128 + t] = s;
            }
        }
    }
}

// ---------------- fused conv1 + gating + conv2 + attention scatter ----------------
__global__ void __launch_bounds__(128) edge_main_kernel(
    const float* __restrict__ Wc1, const float* __restrict__ Wxj,
    const float* __restrict__ Wc2, const float* __restrict__ rl,
    const int* __restrict__ eidx)
{
    __shared__ float bufA[128][36];   // x_edge tile, later val tile  [c][e]
    __shared__ float xsb [64][36];    // xs tile (for xj_proj)
    __shared__ float rl_s[32][8];
    __shared__ float ee_s[32][8];
    __shared__ int src_s[32], tgt_s[32];
    int e0 = blockIdx.x * 32, t = threadIdx.x;
    if (t < 32)      src_s[t]    = eidx[e0 + t];
    else if (t < 64) tgt_s[t-32] = eidx[NE + e0 + t - 32];
    for (int i = t; i < 256; i += 128) { int e = i>>3, j = i&7; rl_s[e][j] = rl[(e0+e)*8 + j]; }
    for (int i = t; i < 256; i += 128) { int e = i>>3, j = i&7; ee_s[e][j] = g_e[(e0+e)*8 + j]; }
    __syncthreads();

    for (int k = 0; k < 9; k++) {
        int deg = (k == 0) ? 0 : ((k < 4) ? 1 : 2);
        if (k == 0) {
#pragma unroll
            for (int e = 0; e < 32; e++) bufA[t][e] = g_val0[(e0+e)*128 + t];
            __syncthreads();
        } else {
#pragma unroll
            for (int e = 0; e < 32; e++) {
                float rv = g_rad[(e0+e)*384 + deg*128 + t];
                float xv;
                if (t < 64) { xv = g_xn[src_s[e]*576 + k*64 + t];        xsb[t][e] = xv; }
                else        { xv = g_xn[tgt_s[e]*576 + k*64 + (t-64)]; }
                bufA[t][e] = xv * rv;
            }
            __syncthreads();
            float acc1[32], acc2[32];
#pragma unroll
            for (int e = 0; e < 32; e++) { acc1[e] = 0.f; acc2[e] = 0.f; }
            const float* W = Wc1 + deg*16384 + t;
#pragma unroll 4
            for (int c = 0; c < 128; c++) {
                float w = W[c*128];
                const float4* xr = (const float4*)&bufA[c][0];
#pragma unroll
                for (int e4 = 0; e4 < 8; e4++) {
                    float4 xv = xr[e4];
                    acc1[e4*4+0] += w*xv.x; acc1[e4*4+1] += w*xv.y;
                    acc1[e4*4+2] += w*xv.z; acc1[e4*4+3] += w*xv.w;
                }
            }
            const float* W2 = Wxj + t;
#pragma unroll 2
            for (int c = 0; c < 64; c++) {
                float w = W2[c*128];
                const float4* xr = (const float4*)&xsb[c][0];
#pragma unroll
                for (int e4 = 0; e4 < 8; e4++) {
                    float4 xv = xr[e4];
                    acc2[e4*4+0] += w*xv.x; acc2[e4*4+1] += w*xv.y;
                    acc2[e4*4+2] += w*xv.z; acc2[e4*4+3] += w*xv.w;
                }
            }
            __syncthreads();   // done reading bufA/xsb
            int l = (k < 4) ? 0 : 1;   // EXP1[k-1]
            int base = e0*256 + l*128 + t;
#pragma unroll
            for (int e = 0; e < 32; e++) {
                float gd = g_gdir[base + e*256];
                float gt = g_gten[base + e*256];
                bufA[t][e] = acc1[e] + rl_s[e][k-1]*gd + acc2[e]*gt;   // val
            }
            __syncthreads();
        }
        // conv2 + attention-weighted scatter
        float acc3[32];
#pragma unroll
        for (int e = 0; e < 32; e++) acc3[e] = 0.f;
        const float* W3 = Wc2 + deg*16384 + t;
#pragma unroll 4
        for (int d = 0; d < 128; d++) {
            float w = W3[d*128];
            const float4* xr = (const float4*)&bufA[d][0];
#pragma unroll
            for (int e4 = 0; e4 < 8; e4++) {
                float4 xv = xr[e4];
                acc3[e4*4+0] += w*xv.x; acc3[e4*4+1] += w*xv.y;
                acc3[e4*4+2] += w*xv.z; acc3[e4*4+3] += w*xv.w;
            }
        }
        int h = t >> 4;
#pragma unroll
        for (int e = 0; e < 32; e++)
            atomicAdd(&g_num[tgt_s[e]*1152 + k*128 + t], acc3[e]*ee_s[e][h]);
        __syncthreads();
    }
}

// ---------------- node: x1 = x + so3_linear(node_out, W_proj, b_proj) ----------------
__global__ void __launch_bounds__(128) proj_kernel(
    const float* __restrict__ x, const float* __restrict__ Wp, const float* __restrict__ bp)
{
    int n = blockIdx.x, t = threadIdx.x;
    __shared__ float no_s[1152];
    __shared__ float den_s[8];
    if (t < 8) den_s[t] = g_den[n*8 + t] + 1e-30f;
    __syncthreads();
    for (int i = t; i < 1152; i += 128) {
        int o = i & 127;
        no_s[i] = g_num[n*1152 + i] / den_s[o >> 4];
    }
    __syncthreads();
    for (int idx = t; idx < 576; idx += 128) {
        int k = idx >> 6, d = idx & 63;
        int deg = c_EXPAND[k];
        float acc = (k == 0) ? bp[d] : 0.f;
        const float* W = Wp + deg*8192 + d;
        const float* v = &no_s[k*128];
#pragma unroll 4
        for (int c = 0; c < 128; c++) acc += v[c] * W[c*64];
        g_x1[n*576 + idx] = x[n*576 + idx] + acc;
    }
}

// ---------------- node: gate = yn[:,0]@W_gate + b_gate ----------------
__global__ void __launch_bounds__(128) gate_kernel(
    const float* __restrict__ Wg, const float* __restrict__ bg)
{
    int n = blockIdx.x, t = threadIdx.x;
    __shared__ float y0[64];
    if (t < 64) y0[t] = g_yn[n*576 + t];
    __syncthreads();
    float acc = bg[t];
    const float* W = Wg + t;
#pragma unroll 4
    for (int c = 0; c < 64; c++) acc += y0[c] * W[c*128];
    g_gsil[n*128 + t] = acc * sigm(acc);
    g_gsig[n*128 + t] = sigm(acc);
}

// ---------------- node: FFN + second residual -> output ----------------
__global__ void __launch_bounds__(128) ffn_kernel(
    const float* __restrict__ Wf1, const float* __restrict__ Wf2,
    const float* __restrict__ bf2, float* __restrict__ out)
{
    int n = blockIdx.x, t = threadIdx.x;
    __shared__ float yn_s[576];
    __shared__ float h_s[1152];
    for (int i = t; i < 576; i += 128) yn_s[i] = g_yn[n*576 + i];
    __syncthreads();
    float gs = g_gsig[n*128 + t];
#pragma unroll
    for (int k = 1; k < 9; k++) {
        int deg = (k < 4) ? 1 : 2;
        float acc = 0.f;
        const float* W = Wf1 + deg*8192 + t;
        const float* v = &yn_s[k*64];
#pragma unroll 4
        for (int c = 0; c < 64; c++) acc += v[c] * W[c*128];
        h_s[k*128 + t] = acc * gs;
    }
    h_s[t] = g_gsil[n*128 + t];
    __syncthreads();
    for (int idx = t; idx < 576; idx += 128) {
        int k = idx >> 6, d = idx & 63;
        int deg = c_EXPAND[k];
        float acc = (k == 0) ? bf2[d] : 0.f;
        const float* W = Wf2 + deg*8192 + d;
        const float* v = &h_s[k*128];
#pragma unroll 4
        for (int c = 0; c < 128; c++) acc += v[c] * W[c*64];
        out[n*576 + idx] = g_x1[n*576 + idx] + acc;
    }
}

// ---------------- launch ----------------
extern "C" void kernel_launch(void* const* d_in, const int* in_sizes, int n_in,
                              void* d_out, int out_size)
{
    const float* x     = (const float*)d_in[0];
    const float* edist = (const float*)d_in[1];
    const float* rl    = (const float*)d_in[2];
    const float* semb  = (const float*)d_in[3];
    const float* temb  = (const float*)d_in[4];
    const float* W1    = (const float*)d_in[5];
    const float* b1    = (const float*)d_in[6];
    const float* W2    = (const float*)d_in[7];
    const float* b2    = (const float*)d_in[8];
    const float* Wc1   = (const float*)d_in[9];
    const float* Wm0   = (const float*)d_in[10];
    const float* lng   = (const float*)d_in[11];
    const float* lnb   = (const float*)d_in[12];
    const float* adot  = (const float*)d_in[13];
    const float* Wxj   = (const float*)d_in[14];
    const float* Wc2   = (const float*)d_in[15];
    const float* Wp    = (const float*)d_in[16];
    const float* bp    = (const float*)d_in[17];
    const float* Wg    = (const float*)d_in[18];
    const float* bg    = (const float*)d_in[19];
    const float* Wf1   = (const float*)d_in[20];
    /* b_ffn1 (d_in[21]) is only added at k=0, whose slot is replaced by silu(g) -> unused */
    const float* Wf2   = (const float*)d_in[22];
    const float* bf2   = (const float*)d_in[23];
    const int*   anum  = (const int*)d_in[24];
    const int*   eidx  = (const int*)d_in[25];
    float* out = (float*)d_out;

    float *p_xn, *p_x1, *p_yn;
    cudaGetSymbolAddress((void**)&p_xn, g_xn);
    cudaGetSymbolAddress((void**)&p_x1, g_x1);
    cudaGetSymbolAddress((void**)&p_yn, g_yn);

    zero_kernel<<<(NN*1152 + 255)/256, 256>>>();
    enorm_kernel<<<NN, 64>>>(x, p_xn);
    rad_kernel<<<NE/16, 128>>>(edist, semb, temb, W1, b1, W2, b2, anum, eidx);
    extra_kernel<<<NE/16, 128>>>(Wm0, lng, lnb, adot, eidx);
    edge_main_kernel<<<NE/32, 128>>>(Wc1, Wxj, Wc2, rl, eidx);
    proj_kernel<<<NN, 128>>>(x, Wp, bp);
    enorm_kernel<<<NN, 64>>>(p_x1, p_yn);
    gate_kernel<<<NN, 128>>>(Wg, bg);
    ffn_kernel<<<NN, 128>>>(Wf1, Wf2, bf2, out);
}

// round 3
// speedup vs baseline: 1.5365x; 1.5365x over previous
#include <cuda_runtime.h>

#define NN 10000
#define NE 80000

__device__ __constant__ int c_EXPAND[9] = {0,1,1,1,2,2,2,2,2};

__device__ float g_xn  [NN*576];
__device__ float g_rad [NE*384];
__device__ float g_val0[NE*128];
__device__ float g_gdir[NE*256];
__device__ float g_gten[NE*256];
__device__ float g_e   [NE*8];
__device__ float g_xjp [NN*1024];   // per-node xj_proj (N, k=1..8, 128)
__device__ float g_num [NN*1152];
__device__ float g_den [NN*8];
__device__ float g_x1  [NN*576];
__device__ float g_yn  [NN*576];
__device__ float g_gsil[NN*128];
__device__ float g_gsig[NN*128];

__device__ __forceinline__ float sigm(float z) { return 1.f / (1.f + __expf(-z)); }

__device__ __forceinline__ void red4(float* p, float a, float b, float c, float d) {
    asm volatile("red.global.add.v4.f32 [%0], {%1,%2,%3,%4};"
                 :: "l"(p), "f"(a), "f"(b), "f"(c), "f"(d) : "memory");
}

// Register-tiled GEMM: thread computes 4 cols x 8 edges. X row stride = 36.
__device__ __forceinline__ void gemm_acc(const float* __restrict__ W, int wstride,
                                         const float* __restrict__ Xb, float* acc)
{
#pragma unroll 4
    for (int c = 0; c < 128; c++, W += wstride, Xb += 36) {
        float4 w  = *(const float4*)W;
        float4 xa = *(const float4*)Xb;
        float4 xb = *(const float4*)(Xb + 4);
        acc[ 0] += w.x*xa.x; acc[ 1] += w.x*xa.y; acc[ 2] += w.x*xa.z; acc[ 3] += w.x*xa.w;
        acc[ 4] += w.x*xb.x; acc[ 5] += w.x*xb.y; acc[ 6] += w.x*xb.z; acc[ 7] += w.x*xb.w;
        acc[ 8] += w.y*xa.x; acc[ 9] += w.y*xa.y; acc[10] += w.y*xa.z; acc[11] += w.y*xa.w;
        acc[12] += w.y*xb.x; acc[13] += w.y*xb.y; acc[14] += w.y*xb.z; acc[15] += w.y*xb.w;
        acc[16] += w.z*xa.x; acc[17] += w.z*xa.y; acc[18] += w.z*xa.z; acc[19] += w.z*xa.w;
        acc[20] += w.z*xb.x; acc[21] += w.z*xb.y; acc[22] += w.z*xb.z; acc[23] += w.z*xb.w;
        acc[24] += w.w*xa.x; acc[25] += w.w*xa.y; acc[26] += w.w*xa.z; acc[27] += w.w*xa.w;
        acc[28] += w.w*xb.x; acc[29] += w.w*xb.y; acc[30] += w.w*xb.z; acc[31] += w.w*xb.w;
    }
}

__global__ void zero_kernel() {
    int i = blockIdx.x * blockDim.x + threadIdx.x;
    if (i < NN*1152) g_num[i] = 0.f;
    if (i < NN*8)    g_den[i] = 0.f;
}

__global__ void enorm_kernel(const float* __restrict__ src, float* __restrict__ dst) {
    int n = blockIdx.x, c = threadIdx.x;
    const float* p = src + n*576 + c;
    float v[9];
#pragma unroll
    for (int k = 0; k < 9; k++) v[k] = p[k*64];
    float s0 = v[0]*v[0];
    float s1 = v[1]*v[1] + v[2]*v[2] + v[3]*v[3];
    float s2 = v[4]*v[4] + v[5]*v[5] + v[6]*v[6] + v[7]*v[7] + v[8]*v[8];
#pragma unroll
    for (int off = 16; off; off >>= 1) {
        s0 += __shfl_xor_sync(0xffffffffu, s0, off);
        s1 += __shfl_xor_sync(0xffffffffu, s1, off);
        s2 += __shfl_xor_sync(0xffffffffu, s2, off);
    }
    __shared__ float red[3][2];
    if ((c & 31) == 0) { red[0][c>>5] = s0; red[1][c>>5] = s1; red[2][c>>5] = s2; }
    __syncthreads();
    float sc0 = rsqrtf((red[0][0]+red[0][1]) * (1.f/64.f)  + 1e-6f);
    float sc1 = rsqrtf((red[1][0]+red[1][1]) * (1.f/192.f) + 1e-6f);
    float sc2 = rsqrtf((red[2][0]+red[2][1]) * (1.f/320.f) + 1e-6f);
    float* q = dst + n*576 + c;
    q[0] = v[0]*sc0;
#pragma unroll
    for (int k = 1; k < 4; k++) q[k*64] = v[k]*sc1;
#pragma unroll
    for (int k = 4; k < 9; k++) q[k*64] = v[k]*sc2;
}

// per-node xj_proj
__global__ void __launch_bounds__(128) xjp_kernel(const float* __restrict__ Wxj) {
    int n = blockIdx.x, t = threadIdx.x;
    __shared__ float xs[512];
    for (int i = t; i < 512; i += 128) xs[i] = g_xn[(size_t)n*576 + 64 + i];
    __syncthreads();
#pragma unroll
    for (int k = 0; k < 8; k++) {
        float acc = 0.f;
        const float* v = &xs[k*64];
        const float* W = Wxj + t;
#pragma unroll 4
        for (int c = 0; c < 64; c++) acc += v[c] * W[c*128];
        g_xjp[(size_t)n*1024 + k*128 + t] = acc;
    }
}

// radial MLP, 32 edges/block
__global__ void __launch_bounds__(128) rad_kernel(
    const float* __restrict__ edist, const float* __restrict__ semb,
    const float* __restrict__ temb,  const float* __restrict__ W1,
    const float* __restrict__ b1,    const float* __restrict__ W2,
    const float* __restrict__ b2,    const int* __restrict__ anum,
    const int* __restrict__ eidx)
{
    __shared__ float ef[128*36];
    __shared__ float h1[128*36];
    __shared__ int zsrc[32], ztgt[32];
    int e0 = blockIdx.x * 32, t = threadIdx.x;
    int cg = t & 31, eg8 = (t >> 5) * 8;
    if (t < 32)      zsrc[t]    = anum[eidx[e0 + t]];
    else if (t < 64) ztgt[t-32] = anum[eidx[NE + e0 + t - 32]];
    __syncthreads();
    {   // stage ef[c][e]
        int e = t >> 2, q = t & 3;
        const float4* xp;
        if (q < 2)      xp = (const float4*)&edist[(size_t)(e0+e)*64 + q*32];
        else if (q==2)  xp = (const float4*)&semb[(size_t)zsrc[e]*32];
        else            xp = (const float4*)&temb[(size_t)ztgt[e]*32];
        float* col = ef + e; int cb = q*32;
#pragma unroll
        for (int i4 = 0; i4 < 8; i4++) {
            float4 v = xp[i4];
            col[(cb+i4*4+0)*36] = v.x; col[(cb+i4*4+1)*36] = v.y;
            col[(cb+i4*4+2)*36] = v.z; col[(cb+i4*4+3)*36] = v.w;
        }
    }
    __syncthreads();
    {
        float acc[32];
#pragma unroll
        for (int i = 0; i < 32; i++) acc[i] = 0.f;
        gemm_acc(W1 + cg*4, 128, ef + eg8, acc);
        float4 bb = *(const float4*)&b1[cg*4];
        float bv[4] = {bb.x, bb.y, bb.z, bb.w};
#pragma unroll
        for (int dd = 0; dd < 4; dd++) {
#pragma unroll
            for (int ee = 0; ee < 8; ee++) {
                float z = acc[dd*8+ee] + bv[dd];
                acc[dd*8+ee] = z * sigm(z);
            }
            *(float4*)&h1[(cg*4+dd)*36 + eg8]     = make_float4(acc[dd*8+0],acc[dd*8+1],acc[dd*8+2],acc[dd*8+3]);
            *(float4*)&h1[(cg*4+dd)*36 + eg8 + 4] = make_float4(acc[dd*8+4],acc[dd*8+5],acc[dd*8+6],acc[dd*8+7]);
        }
    }
    __syncthreads();
    for (int j = 0; j < 3; j++) {
        float acc[32];
#pragma unroll
        for (int i = 0; i < 32; i++) acc[i] = 0.f;
        gemm_acc(W2 + j*128 + cg*4, 384, h1 + eg8, acc);
        float4 bb = *(const float4*)&b2[j*128 + cg*4];
#pragma unroll
        for (int ee = 0; ee < 8; ee++)
            *(float4*)&g_rad[(size_t)(e0+eg8+ee)*384 + j*128 + cg*4] =
                make_float4(acc[ee]+bb.x, acc[8+ee]+bb.y, acc[16+ee]+bb.z, acc[24+ee]+bb.w);
    }
}

// extra: gates / val0 / logits, 32 edges/block
__global__ void __launch_bounds__(128) extra_kernel(
    const float* __restrict__ Wm0, const float* __restrict__ lng,
    const float* __restrict__ lnb, const float* __restrict__ adot,
    const int* __restrict__ eidx)
{
    __shared__ float xe0[128*36];
    __shared__ float alph[32*132];
    __shared__ int src_s[32], tgt_s[32];
    int e0 = blockIdx.x * 32, t = threadIdx.x;
    int cg = t & 31, eg8 = (t >> 5) * 8;
    if (t < 32)      src_s[t]    = eidx[e0 + t];
    else if (t < 64) tgt_s[t-32] = eidx[NE + e0 + t - 32];
    __syncthreads();
    {
        int e = t >> 2, q = t & 3;
        const float4* rp = (const float4*)&g_rad[(size_t)(e0+e)*384 + q*32];
        const float4* xp = (q < 2)
            ? (const float4*)&g_xn[(size_t)src_s[e]*576 + q*32]
            : (const float4*)&g_xn[(size_t)tgt_s[e]*576 + (q-2)*32];
        float* col = xe0 + e; int cb = q*32;
#pragma unroll
        for (int i4 = 0; i4 < 8; i4++) {
            float4 xv = xp[i4], rv = rp[i4];
            col[(cb+i4*4+0)*36] = xv.x*rv.x; col[(cb+i4*4+1)*36] = xv.y*rv.y;
            col[(cb+i4*4+2)*36] = xv.z*rv.z; col[(cb+i4*4+3)*36] = xv.w*rv.w;
        }
    }
    __syncthreads();
    for (int oc = 0; oc < 7; oc++) {
        float acc[32];
#pragma unroll
        for (int i = 0; i < 32; i++) acc[i] = 0.f;
        gemm_acc(Wm0 + oc*128 + cg*4, 896, xe0 + eg8, acc);
        if (oc < 2) {
#pragma unroll
            for (int ee = 0; ee < 8; ee++)
                *(float4*)&alph[(eg8+ee)*132 + cg*4] =
                    make_float4(acc[ee], acc[8+ee], acc[16+ee], acc[24+ee]);
            __syncthreads();
            {
                int e = t >> 2, h4 = t & 3, h = oc*4 + h4;
                const float* ap = &alph[e*132 + h4*32];
                float m = 0.f, m2 = 0.f;
#pragma unroll
                for (int a = 0; a < 32; a++) { float v = ap[a]; m += v; m2 += v*v; }
                m *= (1.f/32.f);
                float rs = rsqrtf(m2*(1.f/32.f) - m*m + 1e-5f);
                float logit = 0.f;
#pragma unroll
                for (int a = 0; a < 32; a++) {
                    float an = (ap[a] - m)*rs*lng[a] + lnb[a];
                    logit += (0.2f*an + 0.8f*an*sigm(an)) * adot[h*32 + a];
                }
                float eex = __expf(logit);
                g_e[(size_t)(e0+e)*8 + h] = eex;
                atomicAdd(&g_den[(size_t)tgt_s[e]*8 + h], eex);
            }
            __syncthreads();
        } else if (oc == 2) {
#pragma unroll
            for (int ee = 0; ee < 8; ee++) {
                float z0 = acc[ee], z1 = acc[8+ee], z2 = acc[16+ee], z3 = acc[24+ee];
                *(float4*)&g_val0[(size_t)(e0+eg8+ee)*128 + cg*4] =
                    make_float4(z0*sigm(z0), z1*sigm(z1), z2*sigm(z2), z3*sigm(z3));
            }
        } else {
            int which = oc - 3;
            float* base = (which < 2) ? g_gdir : g_gten;
            int l = which & 1;
#pragma unroll
            for (int ee = 0; ee < 8; ee++)
                *(float4*)&base[(size_t)(e0+eg8+ee)*256 + l*128 + cg*4] =
                    make_float4(sigm(acc[ee]), sigm(acc[8+ee]), sigm(acc[16+ee]), sigm(acc[24+ee]));
        }
    }
}

// fused conv1 + gating + conv2 + attention scatter, 32 edges/block
__global__ void __launch_bounds__(128) edge_main_kernel(
    const float* __restrict__ Wc1, const float* __restrict__ Wc2,
    const float* __restrict__ rl,  const int* __restrict__ eidx)
{
    __shared__ float Xs[128*36];
    __shared__ float Vs[128*36];
    __shared__ float rl_s[32*8], ee_s[32*8];
    __shared__ int src_s[32], tgt_s[32];
    int e0 = blockIdx.x * 32, t = threadIdx.x;
    int cg = t & 31, eg8 = (t >> 5) * 8;
    if (t < 32)      src_s[t]    = eidx[e0 + t];
    else if (t < 64) tgt_s[t-32] = eidx[NE + e0 + t - 32];
    for (int i = t; i < 256; i += 128) {
        int e = i >> 3, j = i & 7;
        rl_s[i] = rl[(size_t)(e0+e)*8 + j];
        ee_s[i] = g_e[(size_t)(e0+e)*8 + j];
    }
    int se = t >> 2, sq = t & 3;

    for (int k = 0; k < 9; k++) {
        int deg = (k == 0) ? 0 : ((k < 4) ? 1 : 2);
        __syncthreads();
        if (k == 0) {
            const float4* vp = (const float4*)&g_val0[(size_t)(e0+se)*128 + sq*32];
            float* col = Vs + se; int cb = sq*32;
#pragma unroll
            for (int i4 = 0; i4 < 8; i4++) {
                float4 v = vp[i4];
                col[(cb+i4*4+0)*36] = v.x; col[(cb+i4*4+1)*36] = v.y;
                col[(cb+i4*4+2)*36] = v.z; col[(cb+i4*4+3)*36] = v.w;
            }
        } else {
            const float4* rp = (const float4*)&g_rad[(size_t)(e0+se)*384 + deg*128 + sq*32];
            const float4* xp = (sq < 2)
                ? (const float4*)&g_xn[(size_t)src_s[se]*576 + k*64 + sq*32]
                : (const float4*)&g_xn[(size_t)tgt_s[se]*576 + k*64 + (sq-2)*32];
            float* col = Xs + se; int cb = sq*32;
#pragma unroll
            for (int i4 = 0; i4 < 8; i4++) {
                float4 xv = xp[i4], rv = rp[i4];
                col[(cb+i4*4+0)*36] = xv.x*rv.x; col[(cb+i4*4+1)*36] = xv.y*rv.y;
                col[(cb+i4*4+2)*36] = xv.z*rv.z; col[(cb+i4*4+3)*36] = xv.w*rv.w;
            }
            __syncthreads();
            float acc[32];
#pragma unroll
            for (int i = 0; i < 32; i++) acc[i] = 0.f;
            gemm_acc(Wc1 + deg*16384 + cg*4, 128, Xs + eg8, acc);
            int l = (k < 4) ? 0 : 1;
#pragma unroll
            for (int ee = 0; ee < 8; ee++) {
                int e = eg8 + ee;
                size_t eb = (size_t)(e0 + e);
                float4 gd = *(const float4*)&g_gdir[eb*256 + l*128 + cg*4];
                float4 gt = *(const float4*)&g_gten[eb*256 + l*128 + cg*4];
                float4 xj = *(const float4*)&g_xjp[(size_t)src_s[e]*1024 + (k-1)*128 + cg*4];
                float r = rl_s[e*8 + (k-1)];
                acc[ee]    += r*gd.x + xj.x*gt.x;
                acc[8+ee]  += r*gd.y + xj.y*gt.y;
                acc[16+ee] += r*gd.z + xj.z*gt.z;
                acc[24+ee] += r*gd.w + xj.w*gt.w;
            }
#pragma unroll
            for (int dd = 0; dd < 4; dd++) {
                *(float4*)&Vs[(cg*4+dd)*36 + eg8]     = make_float4(acc[dd*8+0],acc[dd*8+1],acc[dd*8+2],acc[dd*8+3]);
                *(float4*)&Vs[(cg*4+dd)*36 + eg8 + 4] = make_float4(acc[dd*8+4],acc[dd*8+5],acc[dd*8+6],acc[dd*8+7]);
            }
        }
        __syncthreads();
        float acc[32];
#pragma unroll
        for (int i = 0; i < 32; i++) acc[i] = 0.f;
        gemm_acc(Wc2 + deg*16384 + cg*4, 128, Vs + eg8, acc);
        int h = cg >> 2;
#pragma unroll
        for (int ee = 0; ee < 8; ee++) {
            int e = eg8 + ee;
            float s = ee_s[e*8 + h];
            red4(&g_num[(size_t)tgt_s[e]*1152 + k*128 + cg*4],
                 acc[ee]*s, acc[8+ee]*s, acc[16+ee]*s, acc[24+ee]*s);
        }
    }
}

__global__ void __launch_bounds__(128) proj_kernel(
    const float* __restrict__ x, const float* __restrict__ Wp, const float* __restrict__ bp)
{
    int n = blockIdx.x, t = threadIdx.x;
    __shared__ float no_s[1152];
    __shared__ float den_s[8];
    if (t < 8) den_s[t] = g_den[n*8 + t] + 1e-30f;
    __syncthreads();
    for (int i = t; i < 1152; i += 128)
        no_s[i] = g_num[(size_t)n*1152 + i] / den_s[(i & 127) >> 4];
    __syncthreads();
    for (int idx = t; idx < 576; idx += 128) {
        int k = idx >> 6, d = idx & 63;
        int deg = c_EXPAND[k];
        float acc = (k == 0) ? bp[d] : 0.f;
        const float* W = Wp + deg*8192 + d;
        const float* v = &no_s[k*128];
#pragma unroll 4
        for (int c = 0; c < 128; c++) acc += v[c] * W[c*64];
        g_x1[n*576 + idx] = x[n*576 + idx] + acc;
    }
}

__global__ void __launch_bounds__(128) gate_kernel(
    const float* __restrict__ Wg, const float* __restrict__ bg)
{
    int n = blockIdx.x, t = threadIdx.x;
    __shared__ float y0[64];
    if (t < 64) y0[t] = g_yn[n*576 + t];
    __syncthreads();
    float acc = bg[t];
    const float* W = Wg + t;
#pragma unroll 4
    for (int c = 0; c < 64; c++) acc += y0[c] * W[c*128];
    g_gsil[n*128 + t] = acc * sigm(acc);
    g_gsig[n*128 + t] = sigm(acc);
}

__global__ void __launch_bounds__(128) ffn_kernel(
    const float* __restrict__ Wf1, const float* __restrict__ Wf2,
    const float* __restrict__ bf2, float* __restrict__ out)
{
    int n = blockIdx.x, t = threadIdx.x;
    __shared__ float yn_s[576];
    __shared__ float h_s[1152];
    for (int i = t; i < 576; i += 128) yn_s[i] = g_yn[n*576 + i];
    __syncthreads();
    float gs = g_gsig[n*128 + t];
#pragma unroll
    for (int k = 1; k < 9; k++) {
        int deg = (k < 4) ? 1 : 2;
        float acc = 0.f;
        const float* W = Wf1 + deg*8192 + t;
        const float* v = &yn_s[k*64];
#pragma unroll 4
        for (int c = 0; c < 64; c++) acc += v[c] * W[c*128];
        h_s[k*128 + t] = acc * gs;
    }
    h_s[t] = g_gsil[n*128 + t];
    __syncthreads();
    for (int idx = t; idx < 576; idx += 128) {
        int k = idx >> 6, d = idx & 63;
        int deg = c_EXPAND[k];
        float acc = (k == 0) ? bf2[d] : 0.f;
        const float* W = Wf2 + deg*8192 + d;
        const float* v = &h_s[k*128];
#pragma unroll 4
        for (int c = 0; c < 128; c++) acc += v[c] * W[c*64];
        out[n*576 + idx] = g_x1[n*576 + idx] + acc;
    }
}

extern "C" void kernel_launch(void* const* d_in, const int* in_sizes, int n_in,
                              void* d_out, int out_size)
{
    const float* x     = (const float*)d_in[0];
    const float* edist = (const float*)d_in[1];
    const float* rl    = (const float*)d_in[2];
    const float* semb  = (const float*)d_in[3];
    const float* temb  = (const float*)d_in[4];
    const float* W1    = (const float*)d_in[5];
    const float* b1    = (const float*)d_in[6];
    const float* W2    = (const float*)d_in[7];
    const float* b2    = (const float*)d_in[8];
    const float* Wc1   = (const float*)d_in[9];
    const float* Wm0   = (const float*)d_in[10];
    const float* lng   = (const float*)d_in[11];
    const float* lnb   = (const float*)d_in[12];
    const float* adot  = (const float*)d_in[13];
    const float* Wxj   = (const float*)d_in[14];
    const float* Wc2   = (const float*)d_in[15];
    const float* Wp    = (const float*)d_in[16];
    const float* bp    = (const float*)d_in[17];
    const float* Wg    = (const float*)d_in[18];
    const float* bg    = (const float*)d_in[19];
    const float* Wf1   = (const float*)d_in[20];
    const float* Wf2   = (const float*)d_in[22];
    const float* bf2   = (const float*)d_in[23];
    const int*   anum  = (const int*)d_in[24];
    const int*   eidx  = (const int*)d_in[25];
    float* out = (float*)d_out;

    float *p_xn, *p_x1, *p_yn;
    cudaGetSymbolAddress((void**)&p_xn, g_xn);
    cudaGetSymbolAddress((void**)&p_x1, g_x1);
    cudaGetSymbolAddress((void**)&p_yn, g_yn);

    zero_kernel<<<(NN*1152 + 255)/256, 256>>>();
    enorm_kernel<<<NN, 64>>>(x, p_xn);
    xjp_kernel<<<NN, 128>>>(Wxj);
    rad_kernel<<<NE/32, 128>>>(edist, semb, temb, W1, b1, W2, b2, anum, eidx);
    extra_kernel<<<NE/32, 128>>>(Wm0, lng, lnb, adot, eidx);
    edge_main_kernel<<<NE/32, 128>>>(Wc1, Wc2, rl, eidx);
    proj_kernel<<<NN, 128>>>(x, Wp, bp);
    enorm_kernel<<<NN, 64>>>(p_x1, p_yn);
    gate_kernel<<<NN, 128>>>(Wg, bg);
    ffn_kernel<<<NN, 128>>>(Wf1, Wf2, bf2, out);
}

// round 4
// speedup vs baseline: 2.0324x; 1.3227x over previous
#include <cuda_runtime.h>
#include <cstdint>

#define NN 10000
#define NE 80000

__device__ __constant__ int c_EXPAND[9] = {0,1,1,1,2,2,2,2,2};

// ---------------- scratch ----------------
__device__ float g_xn  [NN*576];
__device__ float g_rad [NE*384];
__device__ float g_val0[NE*128];
__device__ float g_gdir[NE*256];
__device__ float g_gten[NE*256];
__device__ float g_e   [NE*8];
__device__ float g_xjp [NN*1024];
__device__ float g_val [(size_t)NE*1024];   // conv1 output (E, k=1..8, 128)
__device__ float g_num [NN*1152];
__device__ float g_den [NN*8];
__device__ float g_x1  [NN*576];
__device__ float g_yn  [NN*576];
__device__ float g_gsil[NN*128];
__device__ float g_gsig[NN*128];

__device__ __forceinline__ float sigm(float z) { return 1.f / (1.f + __expf(-z)); }

__device__ __forceinline__ uint32_t f2tf(float x) {
    uint32_t r; asm("cvt.rna.tf32.f32 %0, %1;" : "=r"(r) : "f"(x)); return r;
}
__device__ __forceinline__ void red2(float* p, float a, float b) {
    asm volatile("red.global.add.v2.f32 [%0], {%1,%2};" :: "l"(p), "f"(a), "f"(b) : "memory");
}
__device__ __forceinline__ void mma8(float* d, uint32_t a0,uint32_t a1,uint32_t a2,uint32_t a3,
                                     uint32_t b0,uint32_t b1) {
    asm volatile("mma.sync.aligned.m16n8k8.row.col.f32.tf32.tf32.f32 "
                 "{%0,%1,%2,%3},{%4,%5,%6,%7},{%8,%9},{%0,%1,%2,%3};"
                 : "+f"(d[0]),"+f"(d[1]),"+f"(d[2]),"+f"(d[3])
                 : "r"(a0),"r"(a1),"r"(a2),"r"(a3),"r"(b0),"r"(b1));
}

// Warp-tiled GEMM: 64 edges x 128 outs x 128 k. 8 warps: mg=w&1 (32 edges), ng=w>>1 (32 outs).
// Xs: [e][k] stride 132 (tf32 bits). Ws: [k][n] stride 136 (tf32 bits).
// acc[mt*4+nt][4]: c0/c1 = (row e, cols n,n+1), c2/c3 = (row e+8).
__device__ __forceinline__ void gemm_mma(const uint32_t* __restrict__ Ws,
                                         const uint32_t* __restrict__ Xs,
                                         int lane, int mg, int ng, float acc[8][4])
{
    const uint32_t* xb = Xs + (mg*32 + (lane>>2))*132 + (lane&3);
    const uint32_t* wb = Ws + (lane&3)*136 + ng*32 + (lane>>2);
#pragma unroll
    for (int kk = 0; kk < 16; kk++) {
        const uint32_t* xp = xb + kk*8;
        uint32_t a00 = xp[0],       a01 = xp[8*132],    a02 = xp[4],          a03 = xp[8*132+4];
        uint32_t a10 = xp[16*132],  a11 = xp[24*132],   a12 = xp[16*132+4],   a13 = xp[24*132+4];
        const uint32_t* wp = wb + kk*8*136;
        uint32_t b0[4], b1[4];
#pragma unroll
        for (int nt = 0; nt < 4; nt++) { b0[nt] = wp[nt*8]; b1[nt] = wp[4*136 + nt*8]; }
#pragma unroll
        for (int nt = 0; nt < 4; nt++) {
            mma8(acc[nt],   a00,a01,a02,a03, b0[nt], b1[nt]);
            mma8(acc[4+nt], a10,a11,a12,a13, b0[nt], b1[nt]);
        }
    }
}

// stage a 128x128 weight chunk (row-major, leading dim ldw, col offset co) into Ws[k*136+n]
__device__ __forceinline__ void stage_W(uint32_t* Ws, const float* __restrict__ W,
                                        int ldw, int co, int t)
{
    for (int i = t; i < 16384; i += 256) {
        int k = i >> 7, n = i & 127;
        Ws[k*136 + n] = f2tf(W[k*ldw + co + n]);
    }
}

// ---------------- zero / enorm / xjp (scalar, unchanged) ----------------
__global__ void zero_kernel() {
    int i = blockIdx.x * blockDim.x + threadIdx.x;
    if (i < NN*1152) g_num[i] = 0.f;
    if (i < NN*8)    g_den[i] = 0.f;
}

__global__ void enorm_kernel(const float* __restrict__ src, float* __restrict__ dst) {
    int n = blockIdx.x, c = threadIdx.x;
    const float* p = src + n*576 + c;
    float v[9];
#pragma unroll
    for (int k = 0; k < 9; k++) v[k] = p[k*64];
    float s0 = v[0]*v[0];
    float s1 = v[1]*v[1] + v[2]*v[2] + v[3]*v[3];
    float s2 = v[4]*v[4] + v[5]*v[5] + v[6]*v[6] + v[7]*v[7] + v[8]*v[8];
#pragma unroll
    for (int off = 16; off; off >>= 1) {
        s0 += __shfl_xor_sync(0xffffffffu, s0, off);
        s1 += __shfl_xor_sync(0xffffffffu, s1, off);
        s2 += __shfl_xor_sync(0xffffffffu, s2, off);
    }
    __shared__ float red[3][2];
    if ((c & 31) == 0) { red[0][c>>5] = s0; red[1][c>>5] = s1; red[2][c>>5] = s2; }
    __syncthreads();
    float sc0 = rsqrtf((red[0][0]+red[0][1]) * (1.f/64.f)  + 1e-6f);
    float sc1 = rsqrtf((red[1][0]+red[1][1]) * (1.f/192.f) + 1e-6f);
    float sc2 = rsqrtf((red[2][0]+red[2][1]) * (1.f/320.f) + 1e-6f);
    float* q = dst + n*576 + c;
    q[0] = v[0]*sc0;
#pragma unroll
    for (int k = 1; k < 4; k++) q[k*64] = v[k]*sc1;
#pragma unroll
    for (int k = 4; k < 9; k++) q[k*64] = v[k]*sc2;
}

__global__ void __launch_bounds__(128) xjp_kernel(const float* __restrict__ Wxj) {
    int n = blockIdx.x, t = threadIdx.x;
    __shared__ float xs[512];
    for (int i = t; i < 512; i += 128) xs[i] = g_xn[(size_t)n*576 + 64 + i];
    __syncthreads();
#pragma unroll
    for (int k = 0; k < 8; k++) {
        float acc = 0.f;
        const float* v = &xs[k*64];
        const float* W = Wxj + t;
#pragma unroll 4
        for (int c = 0; c < 64; c++) acc += v[c] * W[c*128];
        g_xjp[(size_t)n*1024 + k*128 + t] = acc;
    }
}

// ---------------- radial MLP (tf32 mma), 64 edges/block ----------------
__global__ void __launch_bounds__(256) rad_kernel(
    const float* __restrict__ edist, const float* __restrict__ semb,
    const float* __restrict__ temb,  const float* __restrict__ W1,
    const float* __restrict__ b1,    const float* __restrict__ W2,
    const float* __restrict__ b2,    const int* __restrict__ anum,
    const int* __restrict__ eidx)
{
    extern __shared__ uint32_t sm[];
    uint32_t* ef = sm;            // 8448
    uint32_t* h1 = sm + 8448;     // 8448
    uint32_t* Ws = sm + 16896;    // 17408
    int* zsrc = (int*)(sm + 34304);
    int* ztgt = zsrc + 64;
    int e0 = blockIdx.x * 64, t = threadIdx.x;
    int lane = t & 31, w = t >> 5, mg = w & 1, ng = w >> 1;
    if (t < 64)       zsrc[t]    = anum[eidx[e0 + t]];
    else if (t < 128) ztgt[t-64] = anum[eidx[NE + e0 + t - 64]];
    __syncthreads();
    {   // stage ef [e][k]
        int e = t >> 2, q = t & 3;
        const float4* xp;
        if (q < 2)      xp = (const float4*)&edist[(size_t)(e0+e)*64 + q*32];
        else if (q==2)  xp = (const float4*)&semb[(size_t)zsrc[e]*32];
        else            xp = (const float4*)&temb[(size_t)ztgt[e]*32];
        uint32_t* col = ef + e*132 + q*32;
#pragma unroll
        for (int i4 = 0; i4 < 8; i4++) {
            float4 v = xp[i4];
            uint4 u = make_uint4(f2tf(v.x), f2tf(v.y), f2tf(v.z), f2tf(v.w));
            *(uint4*)(col + i4*4) = u;
        }
    }
    stage_W(Ws, W1, 128, 0, t);
    __syncthreads();
    {
        float acc[8][4] = {};
        gemm_mma(Ws, ef, lane, mg, ng, acc);
        int nbase = ng*32 + (lane&3)*2;
        int ebase = mg*32 + (lane>>2);
#pragma unroll
        for (int nt = 0; nt < 4; nt++) {
            int n = nbase + nt*8;
            float2 bb = *(const float2*)&b1[n];
#pragma unroll
            for (int mt = 0; mt < 2; mt++)
#pragma unroll
            for (int hf = 0; hf < 2; hf++) {
                int el = ebase + mt*16 + hf*8;
                float z0 = acc[mt*4+nt][hf*2+0] + bb.x;
                float z1 = acc[mt*4+nt][hf*2+1] + bb.y;
                uint2 u = make_uint2(f2tf(z0*sigm(z0)), f2tf(z1*sigm(z1)));
                *(uint2*)(h1 + el*132 + n) = u;
            }
        }
    }
    __syncthreads();
    for (int j = 0; j < 3; j++) {
        stage_W(Ws, W2, 384, j*128, t);
        __syncthreads();
        float acc[8][4] = {};
        gemm_mma(Ws, h1, lane, mg, ng, acc);
        int nbase = ng*32 + (lane&3)*2;
        int ebase = mg*32 + (lane>>2);
#pragma unroll
        for (int nt = 0; nt < 4; nt++) {
            int n = nbase + nt*8;
            float2 bb = *(const float2*)&b2[j*128 + n];
#pragma unroll
            for (int mt = 0; mt < 2; mt++)
#pragma unroll
            for (int hf = 0; hf < 2; hf++) {
                int el = ebase + mt*16 + hf*8;
                *(float2*)&g_rad[(size_t)(e0+el)*384 + j*128 + n] =
                    make_float2(acc[mt*4+nt][hf*2+0] + bb.x, acc[mt*4+nt][hf*2+1] + bb.y);
            }
        }
        __syncthreads();
    }
}

// ---------------- extra (tf32 mma): gates / val0 / attention logits ----------------
__global__ void __launch_bounds__(256) extra_kernel(
    const float* __restrict__ Wm0, const float* __restrict__ lng,
    const float* __restrict__ lnb, const float* __restrict__ adot,
    const int* __restrict__ eidx)
{
    extern __shared__ uint32_t sm[];
    uint32_t* Xs = sm;            // 8448
    uint32_t* Ws = sm + 8448;     // 17408
    int* src_s = (int*)(sm + 25856);
    int* tgt_s = src_s + 64;
    int e0 = blockIdx.x * 64, t = threadIdx.x;
    int lane = t & 31, w = t >> 5, mg = w & 1, ng = w >> 1;
    if (t < 64)       src_s[t]    = eidx[e0 + t];
    else if (t < 128) tgt_s[t-64] = eidx[NE + e0 + t - 64];
    __syncthreads();
    {   // stage Xs = x_edge[:,0] * rad0
        int e = t >> 2, q = t & 3;
        const float4* rp = (const float4*)&g_rad[(size_t)(e0+e)*384 + q*32];
        const float4* xp = (q < 2)
            ? (const float4*)&g_xn[(size_t)src_s[e]*576 + q*32]
            : (const float4*)&g_xn[(size_t)tgt_s[e]*576 + (q-2)*32];
        uint32_t* col = Xs + e*132 + q*32;
#pragma unroll
        for (int i4 = 0; i4 < 8; i4++) {
            float4 xv = xp[i4], rv = rp[i4];
            uint4 u = make_uint4(f2tf(xv.x*rv.x), f2tf(xv.y*rv.y), f2tf(xv.z*rv.z), f2tf(xv.w*rv.w));
            *(uint4*)(col + i4*4) = u;
        }
    }
    int nbase = ng*32 + (lane&3)*2;
    int ebase = mg*32 + (lane>>2);
    for (int oc = 0; oc < 7; oc++) {
        __syncthreads();   // Ws reuse guard (also covers initial Xs staging)
        stage_W(Ws, Wm0, 896, oc*128, t);
        __syncthreads();
        float acc[8][4] = {};
        gemm_mma(Ws, Xs, lane, mg, ng, acc);
        if (oc < 2) {
            int h = oc*4 + ng;
            float lg[8], lb[8], ad[8];
#pragma unroll
            for (int nt = 0; nt < 4; nt++) {
                int a = nt*8 + (lane&3)*2;
                float2 v;
                v = *(const float2*)&lng[a];       lg[nt*2] = v.x; lg[nt*2+1] = v.y;
                v = *(const float2*)&lnb[a];       lb[nt*2] = v.x; lb[nt*2+1] = v.y;
                v = *(const float2*)&adot[h*32+a]; ad[nt*2] = v.x; ad[nt*2+1] = v.y;
            }
#pragma unroll
            for (int mt = 0; mt < 2; mt++)
#pragma unroll
            for (int hf = 0; hf < 2; hf++) {
                int el = ebase + mt*16 + hf*8;
                float sum = 0.f, ssq = 0.f;
#pragma unroll
                for (int nt = 0; nt < 4; nt++) {
                    float v0 = acc[mt*4+nt][hf*2+0], v1 = acc[mt*4+nt][hf*2+1];
                    sum += v0 + v1; ssq += v0*v0 + v1*v1;
                }
                sum += __shfl_xor_sync(0xffffffffu, sum, 1);
                sum += __shfl_xor_sync(0xffffffffu, sum, 2);
                ssq += __shfl_xor_sync(0xffffffffu, ssq, 1);
                ssq += __shfl_xor_sync(0xffffffffu, ssq, 2);
                float m = sum * (1.f/32.f);
                float rs = rsqrtf(ssq * (1.f/32.f) - m*m + 1e-5f);
                float logit = 0.f;
#pragma unroll
                for (int nt = 0; nt < 4; nt++) {
#pragma unroll
                    for (int jj = 0; jj < 2; jj++) {
                        float v = acc[mt*4+nt][hf*2+jj];
                        float an = (v - m)*rs*lg[nt*2+jj] + lb[nt*2+jj];
                        logit += (0.2f*an + 0.8f*an*sigm(an)) * ad[nt*2+jj];
                    }
                }
                logit += __shfl_xor_sync(0xffffffffu, logit, 1);
                logit += __shfl_xor_sync(0xffffffffu, logit, 2);
                if ((lane & 3) == 0) {
                    float ex = __expf(logit);
                    g_e[(size_t)(e0+el)*8 + h] = ex;
                    atomicAdd(&g_den[(size_t)tgt_s[el]*8 + h], ex);
                }
            }
        } else if (oc == 2) {
#pragma unroll
            for (int nt = 0; nt < 4; nt++) {
                int n = nbase + nt*8;
#pragma unroll
                for (int mt = 0; mt < 2; mt++)
#pragma unroll
                for (int hf = 0; hf < 2; hf++) {
                    int el = ebase + mt*16 + hf*8;
                    float z0 = acc[mt*4+nt][hf*2+0], z1 = acc[mt*4+nt][hf*2+1];
                    *(float2*)&g_val0[(size_t)(e0+el)*128 + n] =
                        make_float2(z0*sigm(z0), z1*sigm(z1));
                }
            }
        } else {
            int which = oc - 3;
            float* base = (which < 2) ? g_gdir : g_gten;
            int l = which & 1;
#pragma unroll
            for (int nt = 0; nt < 4; nt++) {
                int n = nbase + nt*8;
#pragma unroll
                for (int mt = 0; mt < 2; mt++)
#pragma unroll
                for (int hf = 0; hf < 2; hf++) {
                    int el = ebase + mt*16 + hf*8;
                    *(float2*)&base[(size_t)(e0+el)*256 + l*128 + n] =
                        make_float2(sigm(acc[mt*4+nt][hf*2+0]), sigm(acc[mt*4+nt][hf*2+1]));
                }
            }
        }
    }
}

// ---------------- conv1 (tf32 mma): val = conv1(x_edge) + rl*gdir + xjp*gten ----------------
__global__ void __launch_bounds__(256) conv1_kernel(
    const float* __restrict__ Wc1, const float* __restrict__ rl,
    const int* __restrict__ eidx)
{
    extern __shared__ uint32_t sm[];
    uint32_t* Xs = sm;            // 8448
    uint32_t* Ws = sm + 8448;     // 17408
    float* rl_s = (float*)(sm + 25856);   // 512
    int* src_s = (int*)(sm + 26368);
    int* tgt_s = src_s + 64;
    int e0 = blockIdx.x * 64, t = threadIdx.x;
    int lane = t & 31, w = t >> 5, mg = w & 1, ng = w >> 1;
    if (t < 64)       src_s[t]    = eidx[e0 + t];
    else if (t < 128) tgt_s[t-64] = eidx[NE + e0 + t - 64];
    for (int i = t; i < 512; i += 256) rl_s[i] = rl[(size_t)e0*8 + i];
    int nbase = ng*32 + (lane&3)*2;
    int ebase = mg*32 + (lane>>2);
    __syncthreads();
    for (int deg = 1; deg <= 2; deg++) {
        stage_W(Ws, Wc1, 128, 0, t);   // placeholder overwritten below (keeps code small)
        // real staging with deg offset:
        for (int i = t; i < 16384; i += 256)
            Ws[(i>>7)*136 + (i&127)] = f2tf(Wc1[deg*16384 + i]);
        __syncthreads();
        int kbeg = (deg == 1) ? 1 : 4, kend = (deg == 1) ? 4 : 9;
        for (int k = kbeg; k < kend; k++) {
            {   // stage Xs
                int e = t >> 2, q = t & 3;
                const float4* rp = (const float4*)&g_rad[(size_t)(e0+e)*384 + deg*128 + q*32];
                const float4* xp = (q < 2)
                    ? (const float4*)&g_xn[(size_t)src_s[e]*576 + k*64 + q*32]
                    : (const float4*)&g_xn[(size_t)tgt_s[e]*576 + k*64 + (q-2)*32];
                uint32_t* col = Xs + e*132 + q*32;
#pragma unroll
                for (int i4 = 0; i4 < 8; i4++) {
                    float4 xv = xp[i4], rv = rp[i4];
                    uint4 u = make_uint4(f2tf(xv.x*rv.x), f2tf(xv.y*rv.y), f2tf(xv.z*rv.z), f2tf(xv.w*rv.w));
                    *(uint4*)(col + i4*4) = u;
                }
            }
            __syncthreads();
            float acc[8][4] = {};
            gemm_mma(Ws, Xs, lane, mg, ng, acc);
            int l = (k < 4) ? 0 : 1;
#pragma unroll
            for (int mt = 0; mt < 2; mt++)
#pragma unroll
            for (int hf = 0; hf < 2; hf++) {
                int el = ebase + mt*16 + hf*8;
                size_t ge = (size_t)(e0 + el);
                float r = rl_s[el*8 + (k-1)];
                size_t gb = ge*256 + l*128;
                size_t xb = (size_t)src_s[el]*1024 + (size_t)(k-1)*128;
                size_t vb = ge*1024 + (size_t)(k-1)*128;
#pragma unroll
                for (int nt = 0; nt < 4; nt++) {
                    int n = nbase + nt*8;
                    float2 gd = *(const float2*)&g_gdir[gb + n];
                    float2 gt = *(const float2*)&g_gten[gb + n];
                    float2 xj = *(const float2*)&g_xjp[xb + n];
                    float v0 = acc[mt*4+nt][hf*2+0] + r*gd.x + xj.x*gt.x;
                    float v1 = acc[mt*4+nt][hf*2+1] + r*gd.y + xj.y*gt.y;
                    *(float2*)&g_val[vb + n] = make_float2(v0, v1);
                }
            }
            __syncthreads();
        }
    }
}

// ---------------- conv2 (tf32 mma) + attention scatter ----------------
__global__ void __launch_bounds__(256) conv2_kernel(
    const float* __restrict__ Wc2, const int* __restrict__ eidx)
{
    extern __shared__ uint32_t sm[];
    uint32_t* Vs = sm;            // 8448
    uint32_t* Ws = sm + 8448;     // 17408
    float* ee_s = (float*)(sm + 25856);   // 512
    int* tgt_s = (int*)(sm + 26368);
    int e0 = blockIdx.x * 64, t = threadIdx.x;
    int lane = t & 31, w = t >> 5, mg = w & 1, ng = w >> 1;
    if (t < 64) tgt_s[t] = eidx[NE + e0 + t];
    for (int i = t; i < 512; i += 256) ee_s[i] = g_e[(size_t)e0*8 + i];
    int nbase = ng*32 + (lane&3)*2;
    int ebase = mg*32 + (lane>>2);
    for (int k = 0; k < 9; k++) {
        int deg = (k == 0) ? 0 : ((k < 4) ? 1 : 2);
        if (k == 0 || k == 1 || k == 4) {
            __syncthreads();
            for (int i = t; i < 16384; i += 256)
                Ws[(i>>7)*136 + (i&127)] = f2tf(Wc2[deg*16384 + i]);
        }
        {   // stage Vs
            int e = t >> 2, q = t & 3;
            const float4* vp = (k == 0)
                ? (const float4*)&g_val0[(size_t)(e0+e)*128 + q*32]
                : (const float4*)&g_val[(size_t)(e0+e)*1024 + (size_t)(k-1)*128 + q*32];
            uint32_t* col = Vs + e*132 + q*32;
#pragma unroll
            for (int i4 = 0; i4 < 8; i4++) {
                float4 v = vp[i4];
                uint4 u = make_uint4(f2tf(v.x), f2tf(v.y), f2tf(v.z), f2tf(v.w));
                *(uint4*)(col + i4*4) = u;
            }
        }
        __syncthreads();
        float acc[8][4] = {};
        gemm_mma(Ws, Vs, lane, mg, ng, acc);
#pragma unroll
        for (int mt = 0; mt < 2; mt++)
#pragma unroll
        for (int hf = 0; hf < 2; hf++) {
            int el = ebase + mt*16 + hf*8;
            size_t nb = (size_t)tgt_s[el]*1152 + (size_t)k*128;
#pragma unroll
            for (int nt = 0; nt < 4; nt++) {
                int n = nbase + nt*8;
                float s = ee_s[el*8 + (n >> 4)];
                red2(&g_num[nb + n], acc[mt*4+nt][hf*2+0]*s, acc[mt*4+nt][hf*2+1]*s);
            }
        }
        __syncthreads();
    }
}

// ---------------- node kernels (unchanged) ----------------
__global__ void __launch_bounds__(128) proj_kernel(
    const float* __restrict__ x, const float* __restrict__ Wp, const float* __restrict__ bp)
{
    int n = blockIdx.x, t = threadIdx.x;
    __shared__ float no_s[1152];
    __shared__ float den_s[8];
    if (t < 8) den_s[t] = g_den[n*8 + t] + 1e-30f;
    __syncthreads();
    for (int i = t; i < 1152; i += 128)
        no_s[i] = g_num[(size_t)n*1152 + i] / den_s[(i & 127) >> 4];
    __syncthreads();
    for (int idx = t; idx < 576; idx += 128) {
        int k = idx >> 6, d = idx & 63;
        int deg = c_EXPAND[k];
        float acc = (k == 0) ? bp[d] : 0.f;
        const float* W = Wp + deg*8192 + d;
        const float* v = &no_s[k*128];
#pragma unroll 4
        for (int c = 0; c < 128; c++) acc += v[c] * W[c*64];
        g_x1[n*576 + idx] = x[n*576 + idx] + acc;
    }
}

__global__ void __launch_bounds__(128) gate_kernel(
    const float* __restrict__ Wg, const float* __restrict__ bg)
{
    int n = blockIdx.x, t = threadIdx.x;
    __shared__ float y0[64];
    if (t < 64) y0[t] = g_yn[n*576 + t];
    __syncthreads();
    float acc = bg[t];
    const float* W = Wg + t;
#pragma unroll 4
    for (int c = 0; c < 64; c++) acc += y0[c] * W[c*128];
    g_gsil[n*128 + t] = acc * sigm(acc);
    g_gsig[n*128 + t] = sigm(acc);
}

__global__ void __launch_bounds__(128) ffn_kernel(
    const float* __restrict__ Wf1, const float* __restrict__ Wf2,
    const float* __restrict__ bf2, float* __restrict__ out)
{
    int n = blockIdx.x, t = threadIdx.x;
    __shared__ float yn_s[576];
    __shared__ float h_s[1152];
    for (int i = t; i < 576; i += 128) yn_s[i] = g_yn[n*576 + i];
    __syncthreads();
    float gs = g_gsig[n*128 + t];
#pragma unroll
    for (int k = 1; k < 9; k++) {
        int deg = (k < 4) ? 1 : 2;
        float acc = 0.f;
        const float* W = Wf1 + deg*8192 + t;
        const float* v = &yn_s[k*64];
#pragma unroll 4
        for (int c = 0; c < 64; c++) acc += v[c] * W[c*128];
        h_s[k*128 + t] = acc * gs;
    }
    h_s[t] = g_gsil[n*128 + t];
    __syncthreads();
    for (int idx = t; idx < 576; idx += 128) {
        int k = idx >> 6, d = idx & 63;
        int deg = c_EXPAND[k];
        float acc = (k == 0) ? bf2[d] : 0.f;
        const float* W = Wf2 + deg*8192 + d;
        const float* v = &h_s[k*128];
#pragma unroll 4
        for (int c = 0; c < 128; c++) acc += v[c] * W[c*64];
        out[n*576 + idx] = g_x1[n*576 + idx] + acc;
    }
}

// ---------------- launch ----------------
extern "C" void kernel_launch(void* const* d_in, const int* in_sizes, int n_in,
                              void* d_out, int out_size)
{
    const float* x     = (const float*)d_in[0];
    const float* edist = (const float*)d_in[1];
    const float* rl    = (const float*)d_in[2];
    const float* semb  = (const float*)d_in[3];
    const float* temb  = (const float*)d_in[4];
    const float* W1    = (const float*)d_in[5];
    const float* b1    = (const float*)d_in[6];
    const float* W2    = (const float*)d_in[7];
    const float* b2    = (const float*)d_in[8];
    const float* Wc1   = (const float*)d_in[9];
    const float* Wm0   = (const float*)d_in[10];
    const float* lng   = (const float*)d_in[11];
    const float* lnb   = (const float*)d_in[12];
    const float* adot  = (const float*)d_in[13];
    const float* Wxj   = (const float*)d_in[14];
    const float* Wc2   = (const float*)d_in[15];
    const float* Wp    = (const float*)d_in[16];
    const float* bp    = (const float*)d_in[17];
    const float* Wg    = (const float*)d_in[18];
    const float* bg    = (const float*)d_in[19];
    const float* Wf1   = (const float*)d_in[20];
    const float* Wf2   = (const float*)d_in[22];
    const float* bf2   = (const float*)d_in[23];
    const int*   anum  = (const int*)d_in[24];
    const int*   eidx  = (const int*)d_in[25];
    float* out = (float*)d_out;

    float *p_xn, *p_x1, *p_yn;
    cudaGetSymbolAddress((void**)&p_xn, g_xn);
    cudaGetSymbolAddress((void**)&p_x1, g_x1);
    cudaGetSymbolAddress((void**)&p_yn, g_yn);

    static bool attr_set = false;
    if (!attr_set) {
        cudaFuncSetAttribute(rad_kernel,   cudaFuncAttributeMaxDynamicSharedMemorySize, 137728);
        cudaFuncSetAttribute(extra_kernel, cudaFuncAttributeMaxDynamicSharedMemorySize, 103936);
        cudaFuncSetAttribute(conv1_kernel, cudaFuncAttributeMaxDynamicSharedMemorySize, 105984);
        cudaFuncSetAttribute(conv2_kernel, cudaFuncAttributeMaxDynamicSharedMemorySize, 105728);
        attr_set = true;
    }

    zero_kernel<<<(NN*1152 + 255)/256, 256>>>();
    enorm_kernel<<<NN, 64>>>(x, p_xn);
    xjp_kernel<<<NN, 128>>>(Wxj);
    rad_kernel<<<NE/64, 256, 137728>>>(edist, semb, temb, W1, b1, W2, b2, anum, eidx);
    extra_kernel<<<NE/64, 256, 103936>>>(Wm0, lng, lnb, adot, eidx);
    conv1_kernel<<<NE/64, 256, 105984>>>(Wc1, rl, eidx);
    conv2_kernel<<<NE/64, 256, 105728>>>(Wc2, eidx);
    proj_kernel<<<NN, 128>>>(x, Wp, bp);
    enorm_kernel<<<NN, 64>>>(p_x1, p_yn);
    gate_kernel<<<NN, 128>>>(Wg, bg);
    ffn_kernel<<<NN, 128>>>(Wf1, Wf2, bf2, out);
}

// round 5
// speedup vs baseline: 2.5012x; 1.2307x over previous
#include <cuda_runtime.h>
#include <cstdint>

#define NN 10000
#define NE 80000

__device__ __constant__ int c_EXPAND[9] = {0,1,1,1,2,2,2,2,2};

__device__ float g_xn  [NN*576];
__device__ float g_rad [NE*384];
__device__ float g_val0[NE*128];
__device__ float g_gdir[NE*256];
__device__ float g_gten[NE*256];
__device__ float g_e   [NE*8];
__device__ float g_xjp [NN*1024];
__device__ float g_val [(size_t)NE*1024];
__device__ float g_num [NN*1152];
__device__ float g_den [NN*8];
__device__ float g_x1  [NN*576];
__device__ float g_yn  [NN*576];
__device__ float g_gsil[NN*128];
__device__ float g_gsig[NN*128];

__device__ __forceinline__ float sigm(float z) { return 1.f / (1.f + __expf(-z)); }

__device__ __forceinline__ uint32_t f2tf(float x) {
    uint32_t r; asm("cvt.rna.tf32.f32 %0, %1;" : "=r"(r) : "f"(x)); return r;
}
__device__ __forceinline__ void red2(float* p, float a, float b) {
    asm volatile("red.global.add.v2.f32 [%0], {%1,%2};" :: "l"(p), "f"(a), "f"(b) : "memory");
}
__device__ __forceinline__ void mma8(float* d, uint32_t a0,uint32_t a1,uint32_t a2,uint32_t a3,
                                     uint32_t b0,uint32_t b1) {
    asm volatile("mma.sync.aligned.m16n8k8.row.col.f32.tf32.tf32.f32 "
                 "{%0,%1,%2,%3},{%4,%5,%6,%7},{%8,%9},{%0,%1,%2,%3};"
                 : "+f"(d[0]),"+f"(d[1]),"+f"(d[2]),"+f"(d[3])
                 : "r"(a0),"r"(a1),"r"(a2),"r"(a3),"r"(b0),"r"(b1));
}

// Warp tile: 32 edges x 32 outs. Xs rows stride 132, Ws rows stride 136.
__device__ __forceinline__ void gemm_mma(const uint32_t* __restrict__ Ws,
                                         const uint32_t* __restrict__ Xs,
                                         int lane, int mg, int ng, float acc[8][4], int nk)
{
    const uint32_t* xb = Xs + (mg*32 + (lane>>2))*132 + (lane&3);
    const uint32_t* wb = Ws + (lane&3)*136 + ng*32 + (lane>>2);
    for (int kk = 0; kk < nk; kk++) {
        const uint32_t* xp = xb + kk*8;
        uint32_t a00 = xp[0],      a01 = xp[8*132],   a02 = xp[4],        a03 = xp[8*132+4];
        uint32_t a10 = xp[16*132], a11 = xp[24*132],  a12 = xp[16*132+4], a13 = xp[24*132+4];
        const uint32_t* wp = wb + kk*8*136;
        uint32_t b0[4], b1[4];
#pragma unroll
        for (int nt = 0; nt < 4; nt++) { b0[nt] = wp[nt*8]; b1[nt] = wp[4*136 + nt*8]; }
#pragma unroll
        for (int nt = 0; nt < 4; nt++) {
            mma8(acc[nt],   a00,a01,a02,a03, b0[nt], b1[nt]);
            mma8(acc[4+nt], a10,a11,a12,a13, b0[nt], b1[nt]);
        }
    }
}

__global__ void zero_kernel() {
    size_t i = (size_t)blockIdx.x * blockDim.x + threadIdx.x;
    if (i < NN*1152/4) ((float4*)g_num)[i] = make_float4(0.f,0.f,0.f,0.f);
    if (i < NN*8)      g_den[i] = 0.f;
}

__global__ void enorm_kernel(const float* __restrict__ src, float* __restrict__ dst) {
    int n = blockIdx.x, c = threadIdx.x;
    const float* p = src + n*576 + c;
    float v[9];
#pragma unroll
    for (int k = 0; k < 9; k++) v[k] = p[k*64];
    float s0 = v[0]*v[0];
    float s1 = v[1]*v[1] + v[2]*v[2] + v[3]*v[3];
    float s2 = v[4]*v[4] + v[5]*v[5] + v[6]*v[6] + v[7]*v[7] + v[8]*v[8];
#pragma unroll
    for (int off = 16; off; off >>= 1) {
        s0 += __shfl_xor_sync(0xffffffffu, s0, off);
        s1 += __shfl_xor_sync(0xffffffffu, s1, off);
        s2 += __shfl_xor_sync(0xffffffffu, s2, off);
    }
    __shared__ float red[3][2];
    if ((c & 31) == 0) { red[0][c>>5] = s0; red[1][c>>5] = s1; red[2][c>>5] = s2; }
    __syncthreads();
    float sc0 = rsqrtf((red[0][0]+red[0][1]) * (1.f/64.f)  + 1e-6f);
    float sc1 = rsqrtf((red[1][0]+red[1][1]) * (1.f/192.f) + 1e-6f);
    float sc2 = rsqrtf((red[2][0]+red[2][1]) * (1.f/320.f) + 1e-6f);
    float* q = dst + n*576 + c;
    q[0] = v[0]*sc0;
#pragma unroll
    for (int k = 1; k < 4; k++) q[k*64] = v[k]*sc1;
#pragma unroll
    for (int k = 4; k < 9; k++) q[k*64] = v[k]*sc2;
}

__global__ void __launch_bounds__(128) xjp_kernel(const float* __restrict__ Wxj) {
    int n = blockIdx.x, t = threadIdx.x;
    __shared__ float xs[512];
    for (int i = t; i < 512; i += 128) xs[i] = g_xn[(size_t)n*576 + 64 + i];
    __syncthreads();
#pragma unroll
    for (int k = 0; k < 8; k++) {
        float acc = 0.f;
        const float* v = &xs[k*64];
        const float* W = Wxj + t;
#pragma unroll 4
        for (int c = 0; c < 64; c++) acc += v[c] * W[c*128];
        g_xjp[(size_t)n*1024 + k*128 + t] = acc;
    }
}

// ---------------- radial MLP: 128 edges/block, 512 thr, half-K weight staging ----------------
__global__ void __launch_bounds__(512,2) rad_kernel(
    const float* __restrict__ edist, const float* __restrict__ semb,
    const float* __restrict__ temb,  const float* __restrict__ W1,
    const float* __restrict__ b1,    const float* __restrict__ W2,
    const float* __restrict__ b2,    const int* __restrict__ anum,
    const int* __restrict__ eidx)
{
    extern __shared__ uint32_t sm[];
    uint32_t* ef = sm;            // 128*132 = 16896 (reused as h1)
    uint32_t* Ws = sm + 16896;    // 64*136 = 8704
    int* zsrc = (int*)(sm + 25600);
    int* ztgt = zsrc + 128;
    int e0 = blockIdx.x * 128, t = threadIdx.x;
    int lane = t & 31, w = t >> 5, mg = w & 3, ng = w >> 2;
    if (t < 128)      zsrc[t]     = anum[eidx[e0 + t]];
    else if (t < 256) ztgt[t-128] = anum[eidx[NE + e0 + t - 128]];
    __syncthreads();
    {   // stage ef [e][k]
        int e = t >> 2, q = t & 3;
        const float4* xp;
        if (q < 2)      xp = (const float4*)&edist[(size_t)(e0+e)*64 + q*32];
        else if (q==2)  xp = (const float4*)&semb[(size_t)zsrc[e]*32];
        else            xp = (const float4*)&temb[(size_t)ztgt[e]*32];
        uint32_t* col = ef + e*132 + q*32;
#pragma unroll
        for (int i4 = 0; i4 < 8; i4++) {
            float4 v = xp[i4];
            *(uint4*)(col + i4*4) = make_uint4(f2tf(v.x), f2tf(v.y), f2tf(v.z), f2tf(v.w));
        }
    }
    int nbase = ng*32 + (lane&3)*2;
    int ebase = mg*32 + (lane>>2);
    {   // layer 1
        float acc[8][4] = {};
#pragma unroll
        for (int hk = 0; hk < 2; hk++) {
            __syncthreads();
            for (int i = t; i < 8192; i += 512)
                Ws[(i>>7)*136 + (i&127)] = f2tf(W1[(hk*64 + (i>>7))*128 + (i&127)]);
            __syncthreads();
            gemm_mma(Ws, ef + hk*64, lane, mg, ng, acc, 8);
        }
        __syncthreads();   // all reads of ef done -> safe to overwrite with h1
#pragma unroll
        for (int nt = 0; nt < 4; nt++) {
            int n = nbase + nt*8;
            float2 bb = *(const float2*)&b1[n];
#pragma unroll
            for (int mt = 0; mt < 2; mt++)
#pragma unroll
            for (int hf = 0; hf < 2; hf++) {
                int el = ebase + mt*16 + hf*8;
                float z0 = acc[mt*4+nt][hf*2+0] + bb.x;
                float z1 = acc[mt*4+nt][hf*2+1] + bb.y;
                *(uint2*)(ef + el*132 + n) = make_uint2(f2tf(z0*sigm(z0)), f2tf(z1*sigm(z1)));
            }
        }
    }
    for (int j = 0; j < 3; j++) {
        float acc[8][4] = {};
#pragma unroll
        for (int hk = 0; hk < 2; hk++) {
            __syncthreads();
            for (int i = t; i < 8192; i += 512)
                Ws[(i>>7)*136 + (i&127)] = f2tf(W2[(hk*64 + (i>>7))*384 + j*128 + (i&127)]);
            __syncthreads();
            gemm_mma(Ws, ef + hk*64, lane, mg, ng, acc, 8);
        }
#pragma unroll
        for (int nt = 0; nt < 4; nt++) {
            int n = nbase + nt*8;
            float2 bb = *(const float2*)&b2[j*128 + n];
#pragma unroll
            for (int mt = 0; mt < 2; mt++)
#pragma unroll
            for (int hf = 0; hf < 2; hf++) {
                int el = ebase + mt*16 + hf*8;
                *(float2*)&g_rad[(size_t)(e0+el)*384 + j*128 + n] =
                    make_float2(acc[mt*4+nt][hf*2+0] + bb.x, acc[mt*4+nt][hf*2+1] + bb.y);
            }
        }
    }
}

// ---------------- extra: 128 edges/block, 512 thr, half-K staging ----------------
__global__ void __launch_bounds__(512,2) extra_kernel(
    const float* __restrict__ Wm0, const float* __restrict__ lng,
    const float* __restrict__ lnb, const float* __restrict__ adot,
    const int* __restrict__ eidx)
{
    extern __shared__ uint32_t sm[];
    uint32_t* Xs = sm;            // 16896
    uint32_t* Ws = sm + 16896;    // 8704
    int* src_s = (int*)(sm + 25600);
    int* tgt_s = src_s + 128;
    int e0 = blockIdx.x * 128, t = threadIdx.x;
    int lane = t & 31, w = t >> 5, mg = w & 3, ng = w >> 2;
    if (t < 128)      src_s[t]     = eidx[e0 + t];
    else if (t < 256) tgt_s[t-128] = eidx[NE + e0 + t - 128];
    __syncthreads();
    {
        int e = t >> 2, q = t & 3;
        const float4* rp = (const float4*)&g_rad[(size_t)(e0+e)*384 + q*32];
        const float4* xp = (q < 2)
            ? (const float4*)&g_xn[(size_t)src_s[e]*576 + q*32]
            : (const float4*)&g_xn[(size_t)tgt_s[e]*576 + (q-2)*32];
        uint32_t* col = Xs + e*132 + q*32;
#pragma unroll
        for (int i4 = 0; i4 < 8; i4++) {
            float4 xv = xp[i4], rv = rp[i4];
            *(uint4*)(col + i4*4) =
                make_uint4(f2tf(xv.x*rv.x), f2tf(xv.y*rv.y), f2tf(xv.z*rv.z), f2tf(xv.w*rv.w));
        }
    }
    int nbase = ng*32 + (lane&3)*2;
    int ebase = mg*32 + (lane>>2);
    for (int oc = 0; oc < 7; oc++) {
        float acc[8][4] = {};
#pragma unroll
        for (int hk = 0; hk < 2; hk++) {
            __syncthreads();
            for (int i = t; i < 8192; i += 512)
                Ws[(i>>7)*136 + (i&127)] = f2tf(Wm0[(hk*64 + (i>>7))*896 + oc*128 + (i&127)]);
            __syncthreads();
            gemm_mma(Ws, Xs + hk*64, lane, mg, ng, acc, 8);
        }
        if (oc < 2) {
            int h = oc*4 + ng;
#pragma unroll
            for (int mt = 0; mt < 2; mt++)
#pragma unroll
            for (int hf = 0; hf < 2; hf++) {
                int el = ebase + mt*16 + hf*8;
                float sum = 0.f, ssq = 0.f;
#pragma unroll
                for (int nt = 0; nt < 4; nt++) {
                    float v0 = acc[mt*4+nt][hf*2+0], v1 = acc[mt*4+nt][hf*2+1];
                    sum += v0 + v1; ssq += v0*v0 + v1*v1;
                }
                sum += __shfl_xor_sync(0xffffffffu, sum, 1);
                sum += __shfl_xor_sync(0xffffffffu, sum, 2);
                ssq += __shfl_xor_sync(0xffffffffu, ssq, 1);
                ssq += __shfl_xor_sync(0xffffffffu, ssq, 2);
                float m = sum * (1.f/32.f);
                float rs = rsqrtf(ssq * (1.f/32.f) - m*m + 1e-5f);
                float logit = 0.f;
#pragma unroll
                for (int nt = 0; nt < 4; nt++) {
                    int a = nt*8 + (lane&3)*2;
#pragma unroll
                    for (int jj = 0; jj < 2; jj++) {
                        float v = acc[mt*4+nt][hf*2+jj];
                        float an = (v - m)*rs*lng[a+jj] + lnb[a+jj];
                        logit += (0.2f*an + 0.8f*an*sigm(an)) * adot[h*32 + a + jj];
                    }
                }
                logit += __shfl_xor_sync(0xffffffffu, logit, 1);
                logit += __shfl_xor_sync(0xffffffffu, logit, 2);
                if ((lane & 3) == 0) {
                    float ex = __expf(logit);
                    g_e[(size_t)(e0+el)*8 + h] = ex;
                    atomicAdd(&g_den[(size_t)tgt_s[el]*8 + h], ex);
                }
            }
        } else if (oc == 2) {
#pragma unroll
            for (int nt = 0; nt < 4; nt++) {
                int n = nbase + nt*8;
#pragma unroll
                for (int mt = 0; mt < 2; mt++)
#pragma unroll
                for (int hf = 0; hf < 2; hf++) {
                    int el = ebase + mt*16 + hf*8;
                    float z0 = acc[mt*4+nt][hf*2+0], z1 = acc[mt*4+nt][hf*2+1];
                    *(float2*)&g_val0[(size_t)(e0+el)*128 + n] =
                        make_float2(z0*sigm(z0), z1*sigm(z1));
                }
            }
        } else {
            int which = oc - 3;
            float* base = (which < 2) ? g_gdir : g_gten;
            int l = which & 1;
#pragma unroll
            for (int nt = 0; nt < 4; nt++) {
                int n = nbase + nt*8;
#pragma unroll
                for (int mt = 0; mt < 2; mt++)
#pragma unroll
                for (int hf = 0; hf < 2; hf++) {
                    int el = ebase + mt*16 + hf*8;
                    *(float2*)&base[(size_t)(e0+el)*256 + l*128 + n] =
                        make_float2(sigm(acc[mt*4+nt][hf*2+0]), sigm(acc[mt*4+nt][hf*2+1]));
                }
            }
        }
    }
}

// ---------------- conv1: 64 edges/block, 256 thr, full-K Ws, 2 blocks/SM ----------------
__global__ void __launch_bounds__(256,2) conv1_kernel(
    const float* __restrict__ Wc1, const float* __restrict__ rl,
    const int* __restrict__ eidx)
{
    extern __shared__ uint32_t sm[];
    uint32_t* Xs = sm;            // 8448
    uint32_t* Ws = sm + 8448;     // 17408
    float* rl_s = (float*)(sm + 25856);   // 512
    int* src_s = (int*)(sm + 26368);
    int e0 = blockIdx.x * 64, t = threadIdx.x;
    int lane = t & 31, w = t >> 5, mg = w & 1, ng = w >> 1;
    if (t < 64) src_s[t] = eidx[e0 + t];
    for (int i = t; i < 512; i += 256) rl_s[i] = rl[(size_t)e0*8 + i];
    int nbase = ng*32 + (lane&3)*2;
    int ebase = mg*32 + (lane>>2);
    for (int deg = 1; deg <= 2; deg++) {
        __syncthreads();
        for (int i = t; i < 16384; i += 256)
            Ws[(i>>7)*136 + (i&127)] = f2tf(Wc1[deg*16384 + i]);
        __syncthreads();
        int kbeg = (deg == 1) ? 1 : 4, kend = (deg == 1) ? 4 : 9;
        for (int k = kbeg; k < kend; k++) {
            {
                int e = t >> 2, q = t & 3;
                const float4* rp = (const float4*)&g_rad[(size_t)(e0+e)*384 + deg*128 + q*32];
                const float4* xp = (q < 2)
                    ? (const float4*)&g_xn[(size_t)src_s[e]*576 + k*64 + q*32]
                    : (const float4*)&g_xn[(size_t)eidx[NE + e0 + e]*576 + k*64 + (q-2)*32];
                uint32_t* col = Xs + e*132 + q*32;
#pragma unroll
                for (int i4 = 0; i4 < 8; i4++) {
                    float4 xv = xp[i4], rv = rp[i4];
                    *(uint4*)(col + i4*4) =
                        make_uint4(f2tf(xv.x*rv.x), f2tf(xv.y*rv.y), f2tf(xv.z*rv.z), f2tf(xv.w*rv.w));
                }
            }
            __syncthreads();
            float acc[8][4] = {};
            gemm_mma(Ws, Xs, lane, mg, ng, acc, 16);
            int l = (k < 4) ? 0 : 1;
#pragma unroll
            for (int mt = 0; mt < 2; mt++)
#pragma unroll
            for (int hf = 0; hf < 2; hf++) {
                int el = ebase + mt*16 + hf*8;
                size_t ge = (size_t)(e0 + el);
                float r = rl_s[el*8 + (k-1)];
                size_t gb = ge*256 + l*128;
                size_t xb = (size_t)src_s[el]*1024 + (size_t)(k-1)*128;
                size_t vb = ge*1024 + (size_t)(k-1)*128;
#pragma unroll
                for (int nt = 0; nt < 4; nt++) {
                    int n = nbase + nt*8;
                    float2 gd = *(const float2*)&g_gdir[gb + n];
                    float2 gt = *(const float2*)&g_gten[gb + n];
                    float2 xj = *(const float2*)&g_xjp[xb + n];
                    *(float2*)&g_val[vb + n] = make_float2(
                        acc[mt*4+nt][hf*2+0] + r*gd.x + xj.x*gt.x,
                        acc[mt*4+nt][hf*2+1] + r*gd.y + xj.y*gt.y);
                }
            }
            __syncthreads();
        }
    }
}

// ---------------- conv2 + attention scatter: 64 edges/block, 2 blocks/SM ----------------
__global__ void __launch_bounds__(256,2) conv2_kernel(
    const float* __restrict__ Wc2, const int* __restrict__ eidx)
{
    extern __shared__ uint32_t sm[];
    uint32_t* Vs = sm;            // 8448
    uint32_t* Ws = sm + 8448;     // 17408
    float* ee_s = (float*)(sm + 25856);   // 512
    int* tgt_s = (int*)(sm + 26368);
    int e0 = blockIdx.x * 64, t = threadIdx.x;
    int lane = t & 31, w = t >> 5, mg = w & 1, ng = w >> 1;
    if (t < 64) tgt_s[t] = eidx[NE + e0 + t];
    for (int i = t; i < 512; i += 256) ee_s[i] = g_e[(size_t)e0*8 + i];
    int nbase = ng*32 + (lane&3)*2;
    int ebase = mg*32 + (lane>>2);
    for (int k = 0; k < 9; k++) {
        int deg = (k == 0) ? 0 : ((k < 4) ? 1 : 2);
        if (k == 0 || k == 1 || k == 4) {
            __syncthreads();
            for (int i = t; i < 16384; i += 256)
                Ws[(i>>7)*136 + (i&127)] = f2tf(Wc2[deg*16384 + i]);
        }
        {
            int e = t >> 2, q = t & 3;
            const float4* vp = (k == 0)
                ? (const float4*)&g_val0[(size_t)(e0+e)*128 + q*32]
                : (const float4*)&g_val[(size_t)(e0+e)*1024 + (size_t)(k-1)*128 + q*32];
            uint32_t* col = Vs + e*132 + q*32;
#pragma unroll
            for (int i4 = 0; i4 < 8; i4++) {
                float4 v = vp[i4];
                *(uint4*)(col + i4*4) = make_uint4(f2tf(v.x), f2tf(v.y), f2tf(v.z), f2tf(v.w));
            }
        }
        __syncthreads();
        float acc[8][4] = {};
        gemm_mma(Ws, Vs, lane, mg, ng, acc, 16);
#pragma unroll
        for (int mt = 0; mt < 2; mt++)
#pragma unroll
        for (int hf = 0; hf < 2; hf++) {
            int el = ebase + mt*16 + hf*8;
            size_t nb = (size_t)tgt_s[el]*1152 + (size_t)k*128;
#pragma unroll
            for (int nt = 0; nt < 4; nt++) {
                int n = nbase + nt*8;
                float s = ee_s[el*8 + (n >> 4)];
                red2(&g_num[nb + n], acc[mt*4+nt][hf*2+0]*s, acc[mt*4+nt][hf*2+1]*s);
            }
        }
        __syncthreads();
    }
}

// ---------------- node kernels ----------------
__global__ void __launch_bounds__(128) proj_kernel(
    const float* __restrict__ x, const float* __restrict__ Wp, const float* __restrict__ bp)
{
    int n = blockIdx.x, t = threadIdx.x;
    __shared__ float no_s[1152];
    __shared__ float den_s[8];
    if (t < 8) den_s[t] = g_den[n*8 + t] + 1e-30f;
    __syncthreads();
    for (int i = t; i < 1152; i += 128)
        no_s[i] = g_num[(size_t)n*1152 + i] / den_s[(i & 127) >> 4];
    __syncthreads();
    for (int idx = t; idx < 576; idx += 128) {
        int k = idx >> 6, d = idx & 63;
        int deg = c_EXPAND[k];
        float acc = (k == 0) ? bp[d] : 0.f;
        const float* W = Wp + deg*8192 + d;
        const float* v = &no_s[k*128];
#pragma unroll 4
        for (int c = 0; c < 128; c++) acc += v[c] * W[c*64];
        g_x1[n*576 + idx] = x[n*576 + idx] + acc;
    }
}

__global__ void __launch_bounds__(128) gate_kernel(
    const float* __restrict__ Wg, const float* __restrict__ bg)
{
    int n = blockIdx.x, t = threadIdx.x;
    __shared__ float y0[64];
    if (t < 64) y0[t] = g_yn[n*576 + t];
    __syncthreads();
    float acc = bg[t];
    const float* W = Wg + t;
#pragma unroll 4
    for (int c = 0; c < 64; c++) acc += y0[c] * W[c*128];
    g_gsil[n*128 + t] = acc * sigm(acc);
    g_gsig[n*128 + t] = sigm(acc);
}

__global__ void __launch_bounds__(128) ffn_kernel(
    const float* __restrict__ Wf1, const float* __restrict__ Wf2,
    const float* __restrict__ bf2, float* __restrict__ out)
{
    int n = blockIdx.x, t = threadIdx.x;
    __shared__ float yn_s[576];
    __shared__ float h_s[1152];
    for (int i = t; i < 576; i += 128) yn_s[i] = g_yn[n*576 + i];
    __syncthreads();
    float gs = g_gsig[n*128 + t];
#pragma unroll
    for (int k = 1; k < 9; k++) {
        int deg = (k < 4) ? 1 : 2;
        float acc = 0.f;
        const float* W = Wf1 + deg*8192 + t;
        const float* v = &yn_s[k*64];
#pragma unroll 4
        for (int c = 0; c < 64; c++) acc += v[c] * W[c*128];
        h_s[k*128 + t] = acc * gs;
    }
    h_s[t] = g_gsil[n*128 + t];
    __syncthreads();
    for (int idx = t; idx < 576; idx += 128) {
        int k = idx >> 6, d = idx & 63;
        int deg = c_EXPAND[k];
        float acc = (k == 0) ? bf2[d] : 0.f;
        const float* W = Wf2 + deg*8192 + d;
        const float* v = &h_s[k*128];
#pragma unroll 4
        for (int c = 0; c < 128; c++) acc += v[c] * W[c*64];
        out[n*576 + idx] = g_x1[n*576 + idx] + acc;
    }
}

// ---------------- launch ----------------
extern "C" void kernel_launch(void* const* d_in, const int* in_sizes, int n_in,
                              void* d_out, int out_size)
{
    const float* x     = (const float*)d_in[0];
    const float* edist = (const float*)d_in[1];
    const float* rl    = (const float*)d_in[2];
    const float* semb  = (const float*)d_in[3];
    const float* temb  = (const float*)d_in[4];
    const float* W1    = (const float*)d_in[5];
    const float* b1    = (const float*)d_in[6];
    const float* W2    = (const float*)d_in[7];
    const float* b2    = (const float*)d_in[8];
    const float* Wc1   = (const float*)d_in[9];
    const float* Wm0   = (const float*)d_in[10];
    const float* lng   = (const float*)d_in[11];
    const float* lnb   = (const float*)d_in[12];
    const float* adot  = (const float*)d_in[13];
    const float* Wxj   = (const float*)d_in[14];
    const float* Wc2   = (const float*)d_in[15];
    const float* Wp    = (const float*)d_in[16];
    const float* bp    = (const float*)d_in[17];
    const float* Wg    = (const float*)d_in[18];
    const float* bg    = (const float*)d_in[19];
    const float* Wf1   = (const float*)d_in[20];
    const float* Wf2   = (const float*)d_in[22];
    const float* bf2   = (const float*)d_in[23];
    const int*   anum  = (const int*)d_in[24];
    const int*   eidx  = (const int*)d_in[25];
    float* out = (float*)d_out;

    float *p_xn, *p_x1, *p_yn;
    cudaGetSymbolAddress((void**)&p_xn, g_xn);
    cudaGetSymbolAddress((void**)&p_x1, g_x1);
    cudaGetSymbolAddress((void**)&p_yn, g_yn);

    static bool attr_set = false;
    if (!attr_set) {
        cudaFuncSetAttribute(rad_kernel,   cudaFuncAttributeMaxDynamicSharedMemorySize, 103424);
        cudaFuncSetAttribute(extra_kernel, cudaFuncAttributeMaxDynamicSharedMemorySize, 103424);
        cudaFuncSetAttribute(conv1_kernel, cudaFuncAttributeMaxDynamicSharedMemorySize, 105728);
        cudaFuncSetAttribute(conv2_kernel, cudaFuncAttributeMaxDynamicSharedMemorySize, 105728);
        attr_set = true;
    }

    zero_kernel<<<(NN*1152/4 + 255)/256, 256>>>();
    enorm_kernel<<<NN, 64>>>(x, p_xn);
    xjp_kernel<<<NN, 128>>>(Wxj);
    rad_kernel<<<NE/128, 512, 103424>>>(edist, semb, temb, W1, b1, W2, b2, anum, eidx);
    extra_kernel<<<NE/128, 512, 103424>>>(Wm0, lng, lnb, adot, eidx);
    conv1_kernel<<<NE/64, 256, 105728>>>(Wc1, rl, eidx);
    conv2_kernel<<<NE/64, 256, 105728>>>(Wc2, eidx);
    proj_kernel<<<NN, 128>>>(x, Wp, bp);
    enorm_kernel<<<NN, 64>>>(p_x1, p_yn);
    gate_kernel<<<NN, 128>>>(Wg, bg);
    ffn_kernel<<<NN, 128>>>(Wf1, Wf2, bf2, out);
}